// round 12
// baseline (speedup 1.0000x reference)
#include <cuda_runtime.h>
#include <math.h>

#define B_   128
#define S_   512
#define T_   36
#define STARTT 34
#define ENDT   35
#define NTHREADS 448

// dynamic smem layout (floats):
//  [0, 18432)        exp(feats) (S*T)   (reused as finalize scratch)
//  [18432, 19728)    raw transitions (36*36)
//  [19728, 20304)    ping-pong buffers: 6 chains x 96 (2 bufs x 48; halves @ +0/+24)
//  [20304, 20544)    meet vectors: 6 x 40  (chain c output at MV + 40c, 34 used)
//  [20544, 20576)    RD scratch: ints [0..13] len partials, floats [16..17] gold parts,
//                    [18] gold total, ints [20..25] per-chain Ks
#define EF  0
#define TR  18432
#define PP  19728
#define MV  20304
#define RD  20544
#define SMEM_FLOATS 20608
#define SMEM_BYTES  (SMEM_FLOATS * 4)

typedef unsigned long long ull;

__device__ float g_partial[B_];
__device__ int   g_count = 0;

__device__ __forceinline__ ull ffma2(ull a, ull b, ull c) {
    ull d;
    asm("fma.rn.f32x2 %0, %1, %2, %3;" : "=l"(d) : "l"(a), "l"(b), "l"(c));
    return d;
}
__device__ __forceinline__ ull fadd2(ull a, ull b) {
    ull d;
    asm("add.rn.f32x2 %0, %1, %2;" : "=l"(d) : "l"(a), "l"(b));
    return d;
}
__device__ __forceinline__ ull pack2(float lo, float hi) {
    ull d;
    asm("mov.b64 %0, {%1, %2};" : "=l"(d) : "f"(lo), "f"(hi));
    return d;
}
__device__ __forceinline__ void unpack2(ull v, float& lo, float& hi) {
    asm("mov.b64 {%0, %1}, %2;" : "=f"(lo), "=f"(hi) : "l"(v));
}
__device__ __forceinline__ void bar_arrive64(int id) {
    asm volatile("bar.arrive %0, 64;" :: "r"(id) : "memory");
}
__device__ __forceinline__ void bar_sync64(int id) {
    asm volatile("bar.sync %0, 64;" :: "r"(id) : "memory");
}

// Partial dot over one 17-value half at hb: 16 values as 8 packed pairs + 1 scalar.
__device__ __forceinline__ void half_fma(const float* __restrict__ hb,
                                         const ull* __restrict__ E8, float eS,
                                         ull& acc0, ull& acc1, float& sS, ull& first)
{
    const ulonglong2* W = (const ulonglong2*)hb;
    const ulonglong2 w0 = W[0], w1 = W[1], w2 = W[2], w3 = W[3];
    acc0 = ffma2(w0.x, E8[0], acc0);  acc1 = ffma2(w0.y, E8[1], acc1);
    acc0 = ffma2(w1.x, E8[2], acc0);  acc1 = ffma2(w1.y, E8[3], acc1);
    acc0 = ffma2(w2.x, E8[4], acc0);  acc1 = ffma2(w2.y, E8[5], acc1);
    acc0 = ffma2(w3.x, E8[6], acc0);  acc1 = ffma2(w3.y, E8[7], acc1);
    sS = fmaf(hb[16], eS, sS);
    first = w0.x;
}

#define FWD_STEP(BUF, RENORM, TT) do {                                        \
    if (lane < 17) pb[(BUF) * 48 + ownOff + lane] = p;                        \
    bar_arrive64(myArr);                                                      \
    __syncwarp();                                                             \
    const float eff = sh[EF + (TT) * T_ + j];                                 \
    ull a0 = 0, a1 = 0; float sOwn = 0.0f; ull f0own;                         \
    half_fma(pb + (BUF) * 48 + ownOff, Eown, eOwn, a0, a1, sOwn, f0own);      \
    bar_sync64(mySyn);                                                        \
    ull b0 = 0, b1 = 0; float sOth = 0.0f; ull f0oth;                         \
    half_fma(pb + (BUF) * 48 + othOff, Eoth, eOth, b0, b1, sOth, f0oth);      \
    float tail = eff;                                                         \
    if (RENORM) {                                                             \
        const ull h0 = half ? f0oth : f0own;                                  \
        const unsigned p0b = (unsigned)(h0 & 0xFFFFFFFFull);                  \
        int k = (int)((p0b >> 23) & 0xFF) - 127;                              \
        k = max(-120, min(120, k));                                           \
        Ks += k;                                                              \
        tail = eff * __int_as_float((unsigned)(127 - k) << 23);               \
    }                                                                         \
    const ull r = fadd2(fadd2(a0, b0), fadd2(a1, b1));                        \
    float lo, hi; unpack2(r, lo, hi);                                         \
    p = ((lo + hi) + (sOwn + sOth)) * tail;                                   \
} while (0)

#define BWD_STEP(BUF, RENORM, TT) do {                                        \
    const float q = bc * efc;                                                 \
    if (lane < 17) wb[(BUF) * 48 + ownOff + lane] = q;                        \
    bar_arrive64(myArr);                                                      \
    __syncwarp();                                                             \
    efc = sh[EF + ((TT) - 1) * T_ + j];                                       \
    ull a0 = 0, a1 = 0; float sOwn = 0.0f; ull f0own;                         \
    half_fma(wb + (BUF) * 48 + ownOff, Rown, rOwn, a0, a1, sOwn, f0own);      \
    bar_sync64(mySyn);                                                        \
    ull b0 = 0, b1 = 0; float sOth = 0.0f; ull f0oth;                         \
    half_fma(wb + (BUF) * 48 + othOff, Roth, rOth, b0, b1, sOth, f0oth);      \
    const ull r = fadd2(fadd2(a0, b0), fadd2(a1, b1));                        \
    float lo, hi; unpack2(r, lo, hi);                                         \
    const float y = (lo + hi) + (sOwn + sOth);                                \
    if (RENORM) {                                                             \
        const ull h0 = half ? f0oth : f0own;                                  \
        const unsigned p0b = (unsigned)(h0 & 0xFFFFFFFFull);                  \
        int k = (int)((p0b >> 23) & 0xFF) - 127;                              \
        k = max(-120, min(120, k));                                           \
        Ks += k;                                                              \
        bc = y * __int_as_float((unsigned)(127 - k) << 23);                   \
    } else {                                                                  \
        bc = y;                                                               \
    }                                                                         \
} while (0)

// Forward chain: p_t[j] = ef_t[j] * sum_i p_{t-1}[i] E[i][j], t = tlo..thi.
__device__ __forceinline__ int run_fwd_chain(
    float* __restrict__ sh, int lane, int half, int j,
    int myArr, int mySyn, float* __restrict__ pb,
    float pinit, int tlo, int thi, float* __restrict__ outv)
{
    ull E0[8], E1[8];
    #pragma unroll
    for (int m = 0; m < 8; m++) {
        E0[m] = pack2(__expf(sh[TR + (2 * m) * T_ + j]),
                      __expf(sh[TR + (2 * m + 1) * T_ + j]));
        E1[m] = pack2(__expf(sh[TR + (17 + 2 * m) * T_ + j]),
                      __expf(sh[TR + (18 + 2 * m) * T_ + j]));
    }
    const float e16 = __expf(sh[TR + 16 * T_ + j]);
    const float e33 = __expf(sh[TR + 33 * T_ + j]);
    const ull*  Eown = half ? E1 : E0;
    const ull*  Eoth = half ? E0 : E1;
    const float eOwn = half ? e33 : e16;
    const float eOth = half ? e16 : e33;
    const int   ownOff = half * 24, othOff = 24 - half * 24;

    float p = pinit;
    int Ks = 0;
    int t = tlo;
    while (t + 1 <= thi) { FWD_STEP(0, true, t); FWD_STEP(1, false, t + 1); t += 2; }
    if (t <= thi) { FWD_STEP(0, true, t); }
    if (lane < 17) outv[j] = p;
    return Ks;
}

// Backward chain: y_{t-1}[i] = sum_j E[i][j] ef_t[j] y_t[j], t = thi down to tloex+1.
__device__ __forceinline__ int run_bwd_chain(
    float* __restrict__ sh, int lane, int half, int j,
    int myArr, int mySyn, float* __restrict__ wb,
    float bcinit, int tloex, int thi, float* __restrict__ outv)
{
    ull R0[8], R1[8];
    #pragma unroll
    for (int m = 0; m < 8; m++) {
        R0[m] = pack2(__expf(sh[TR + j * T_ + (2 * m)]),
                      __expf(sh[TR + j * T_ + (2 * m + 1)]));
        R1[m] = pack2(__expf(sh[TR + j * T_ + (17 + 2 * m)]),
                      __expf(sh[TR + j * T_ + (18 + 2 * m)]));
    }
    const float r16 = __expf(sh[TR + j * T_ + 16]);
    const float r33 = __expf(sh[TR + j * T_ + 33]);
    const ull*  Rown = half ? R1 : R0;
    const ull*  Roth = half ? R0 : R1;
    const float rOwn = half ? r33 : r16;
    const float rOth = half ? r16 : r33;
    const int   ownOff = half * 24, othOff = 24 - half * 24;

    float bc  = bcinit;
    float efc = sh[EF + thi * T_ + j];
    int Ks = 0;
    int t = thi;
    while (t - 1 > tloex) { BWD_STEP(0, true, t); BWD_STEP(1, false, t - 1); t -= 2; }
    if (t > tloex) { BWD_STEP(0, true, t); }
    if (lane < 17) outv[j] = bc;
    return Ks;
}

__global__ void __launch_bounds__(NTHREADS, 1)
crf_kernel(const float* __restrict__ feats,
           const float* __restrict__ transitions,
           const int*   __restrict__ mask,
           const int*   __restrict__ tags,
           float*       __restrict__ out)
{
    extern __shared__ float sh[];
    const int tid  = threadIdx.x;
    const int lane = tid & 31;
    const int wid  = tid >> 5;
    const int b    = blockIdx.x;

    // ---- stage exp(feats[b]) (72KB) + raw transitions into smem, coalesced ----
    {
        const float4* fsrc = (const float4*)(feats + (size_t)b * (S_ * T_));
        float4* fdst = (float4*)(sh + EF);
        for (int i = tid; i < (S_ * T_ / 4); i += NTHREADS) {
            float4 v = fsrc[i];
            v.x = __expf(v.x); v.y = __expf(v.y);
            v.z = __expf(v.z); v.w = __expf(v.w);
            fdst[i] = v;
        }
        const float4* tsrc = (const float4*)transitions;
        float4* tdst = (float4*)(sh + TR);
        for (int i = tid; i < (T_ * T_ / 4); i += NTHREADS)
            tdst[i] = tsrc[i];
    }

    // ---- sequence length (mask is a contiguous prefix) ----
    int lsum = 0;
    {
        const int* mrow = mask + b * S_;
        for (int i = tid; i < S_; i += NTHREADS) lsum += mrow[i];
    }
    #pragma unroll
    for (int off = 16; off > 0; off >>= 1)
        lsum += __shfl_xor_sync(0xFFFFFFFFu, lsum, off);
    if (lane == 0) ((int*)(sh + RD))[wid] = lsum;
    __syncthreads();
    int len = 0;
    #pragma unroll
    for (int i = 0; i < 14; i++) len += ((const int*)(sh + RD))[i];
    const int n1 = len >> 2;
    const int n2 = len >> 1;
    const int n3 = n1 + n2;

    const int chain = wid >> 1;                    // 0..5 chains; 6 = gold
    const int half  = wid & 1;
    const int l     = (lane < 17) ? lane : 16;     // pad lanes duplicate col 16
    const int j     = half * 17 + l;               // this lane's column/state

    if (chain < 6) {
        const int myArr = 1 + 2 * chain + half;    // bars 1..12
        const int mySyn = 2 + 2 * chain - half;
        float* pb   = sh + PP + 96 * chain;
        float* outv = sh + MV + 40 * chain;
        int Ks;
        if (chain == 0 || chain == 1 || chain == 3) {
            // fwd chains: 0 = alpha over A, 1 = a_B over B, 3 = a_C over C
            float pinit; int tlo, thi;
            if (chain == 0) {
                pinit = sh[EF + j] * __expf(sh[TR + STARTT * T_ + j]);
                tlo = 1; thi = n1;
            } else if (chain == 1) { pinit = 1.0f; tlo = n1 + 1; thi = n2; }
            else                   { pinit = 1.0f; tlo = n2 + 1; thi = n3; }
            Ks = run_fwd_chain(sh, lane, half, j, myArr, mySyn, pb,
                               pinit, tlo, thi, outv);
        } else {
            // bwd chains: 2 = b_B over B, 4 = b_C over C, 5 = beta over D
            float bcinit; int tloex, thi;
            if (chain == 2)      { bcinit = 1.0f; tloex = n1; thi = n2; }
            else if (chain == 4) { bcinit = 1.0f; tloex = n2; thi = n3; }
            else { bcinit = __expf(sh[TR + j * T_ + ENDT]); tloex = n3; thi = len - 1; }
            Ks = run_bwd_chain(sh, lane, half, j, myArr, mySyn, pb,
                               bcinit, tloex, thi, outv);
        }
        if (half == 0 && lane == 0) ((int*)(sh + RD))[20 + chain] = Ks;
    } else {
        // ===== warps 12,13: gold score (concurrent with all chains) =====
        const int*   trow = tags  + b * S_;
        const float* frow = feats + (size_t)b * (S_ * T_);
        float g = 0.0f;
        for (int t = tid - 384; t < len; t += 64) {
            const int tg = trow[t];
            const int pv = (t == 0) ? STARTT : trow[t - 1];
            g += __ldg(frow + t * T_ + tg) + sh[TR + pv * T_ + tg];
        }
        #pragma unroll
        for (int off = 16; off > 0; off >>= 1)
            g += __shfl_xor_sync(0xFFFFFFFFu, g, off);
        if (lane == 0) sh[RD + 16 + (wid - 12)] = g;
        bar_sync64(13);
        if (tid == 384) {
            const float endE = sh[TR + trow[len - 1] * T_ + ENDT];
            sh[RD + 18] = sh[RD + 16] + sh[RD + 17] + endE;
        }
    }

    __syncthreads();

    // ---- combine (warp 0):
    //  Z = (b_B.alpha)(b_C.a_B)(a_C.beta) / (sum a_B * sum a_C)
    if (wid == 0) {
        const int j0 = 2 * l;
        const float2 av  = *(const float2*)(sh + MV + 0 * 40 + j0);  // alpha_n1
        const float2 abv = *(const float2*)(sh + MV + 1 * 40 + j0);  // a_B
        const float2 bbv = *(const float2*)(sh + MV + 2 * 40 + j0);  // b_B
        const float2 acv = *(const float2*)(sh + MV + 3 * 40 + j0);  // a_C
        const float2 bcv = *(const float2*)(sh + MV + 4 * 40 + j0);  // b_C
        const float2 bv  = *(const float2*)(sh + MV + 5 * 40 + j0);  // beta_n3
        const bool ok = (lane < 17);
        float c1 = ok ? (av.x * bbv.x + av.y * bbv.y) : 0.0f;
        float c2 = ok ? (abv.x * bcv.x + abv.y * bcv.y) : 0.0f;
        float c3 = ok ? (acv.x * bv.x + acv.y * bv.y) : 0.0f;
        float c4 = ok ? (abv.x + abv.y) : 0.0f;
        float c5 = ok ? (acv.x + acv.y) : 0.0f;
        #pragma unroll
        for (int off = 16; off > 0; off >>= 1) {
            c1 += __shfl_xor_sync(0xFFFFFFFFu, c1, off);
            c2 += __shfl_xor_sync(0xFFFFFFFFu, c2, off);
            c3 += __shfl_xor_sync(0xFFFFFFFFu, c3, off);
            c4 += __shfl_xor_sync(0xFFFFFFFFu, c4, off);
            c5 += __shfl_xor_sync(0xFFFFFFFFu, c5, off);
        }
        if (lane == 0) {
            const int* Kp = (const int*)(sh + RD);
            const int Ks = Kp[20 + 0] + Kp[20 + 2] + Kp[20 + 4] + Kp[20 + 5];
            const float fwd = __logf(c1) + __logf(c2) + __logf(c3)
                            - __logf(c4) - __logf(c5)
                            + (float)Ks * 0.6931471805599453f;
            g_partial[b] = fwd - sh[RD + 18];
        }
    }

    // ---- fused finalize: last block reduces all partials (deterministic) ----
    __shared__ int lastflag;
    __threadfence();
    if (tid == 0) lastflag = (atomicAdd(&g_count, 1) == B_ - 1);
    __syncthreads();
    if (lastflag) {
        __threadfence();
        volatile const float* gp = g_partial;
        if (tid < B_) sh[tid] = gp[tid];      // reuse EF region as scratch
        __syncthreads();
        #pragma unroll
        for (int off = 64; off > 0; off >>= 1) {
            if (tid < off) sh[tid] += sh[tid + off];
            __syncthreads();
        }
        if (tid == 0) {
            out[0] = sh[0] * (1.0f / (float)B_);
            g_count = 0;   // reset for next graph replay
        }
    }
}

extern "C" void kernel_launch(void* const* d_in, const int* in_sizes, int n_in,
                              void* d_out, int out_size)
{
    const float* feats = (const float*)d_in[0];
    const float* trans = (const float*)d_in[1];
    const int*   mask  = (const int*)d_in[2];
    const int*   tags  = (const int*)d_in[3];

    cudaFuncSetAttribute((const void*)crf_kernel,
                         cudaFuncAttributeMaxDynamicSharedMemorySize, SMEM_BYTES);
    crf_kernel<<<B_, NTHREADS, SMEM_BYTES>>>(feats, trans, mask, tags, (float*)d_out);
}

// round 15
// speedup vs baseline: 1.0077x; 1.0077x over previous
#include <cuda_runtime.h>
#include <math.h>

#define B_   128
#define S_   512
#define T_   36
#define STARTT 34
#define ENDT   35
#define NTHREADS 320

// dynamic smem layout (floats):
//  [0, 18432)        exp(feats) (S*T)   (reused as finalize scratch)
//  [18432, 19728)    raw transitions (36*36)
//  [19728, 20112)    ping-pong buffers: 4 chains x 96 (2 bufs x 48; halves @ +0/+24)
//  [20112, 20272)    meet vectors: 4 x 40  (chain c output at MV + 40c, 34 used)
//  [20272, 20304)    RD scratch: ints [0..9] len partials, floats [12..13] gold parts,
//                    [14] gold total, ints [16..19] per-chain Ks
#define EF  0
#define TR  18432
#define PP  19728
#define MV  20112
#define RD  20272
#define SMEM_FLOATS 20304
#define SMEM_BYTES  (SMEM_FLOATS * 4)

typedef unsigned long long ull;

__device__ float g_partial[B_];
__device__ int   g_count = 0;

__device__ __forceinline__ ull ffma2(ull a, ull b, ull c) {
    ull d;
    asm("fma.rn.f32x2 %0, %1, %2, %3;" : "=l"(d) : "l"(a), "l"(b), "l"(c));
    return d;
}
__device__ __forceinline__ ull fadd2(ull a, ull b) {
    ull d;
    asm("add.rn.f32x2 %0, %1, %2;" : "=l"(d) : "l"(a), "l"(b));
    return d;
}
__device__ __forceinline__ ull pack2(float lo, float hi) {
    ull d;
    asm("mov.b64 %0, {%1, %2};" : "=l"(d) : "f"(lo), "f"(hi));
    return d;
}
__device__ __forceinline__ void unpack2(ull v, float& lo, float& hi) {
    asm("mov.b64 {%0, %1}, %2;" : "=f"(lo), "=f"(hi) : "l"(v));
}
__device__ __forceinline__ void bar_sync64(int id) {
    asm volatile("bar.sync %0, 64;" :: "r"(id) : "memory");
}

// Partial dot over one 17-value half at hb: 16 values as 8 packed pairs + 1 scalar.
__device__ __forceinline__ void half_fma(const float* __restrict__ hb,
                                         const ull* __restrict__ E8, float eS,
                                         ull& acc0, ull& acc1, float& sS, ull& first)
{
    const ulonglong2* W = (const ulonglong2*)hb;
    const ulonglong2 w0 = W[0], w1 = W[1], w2 = W[2], w3 = W[3];
    acc0 = ffma2(w0.x, E8[0], acc0);  acc1 = ffma2(w0.y, E8[1], acc1);
    acc0 = ffma2(w1.x, E8[2], acc0);  acc1 = ffma2(w1.y, E8[3], acc1);
    acc0 = ffma2(w2.x, E8[4], acc0);  acc1 = ffma2(w2.y, E8[5], acc1);
    acc0 = ffma2(w3.x, E8[6], acc0);  acc1 = ffma2(w3.y, E8[7], acc1);
    sS = fmaf(hb[16], eS, sS);
    first = w0.x;
}

// Single race-free barrier per step: store own half -> syncwarp -> own-half dot
// (hidden in peer skew) -> bar.sync(64) -> other-half dot.
#define FWD_STEP(BUF, RENORM, TT) do {                                        \
    if (lane < 17) pb[(BUF) * 48 + ownOff + lane] = p;                        \
    __syncwarp();                                                             \
    const float eff = sh[EF + (TT) * T_ + j];                                 \
    ull a0 = 0, a1 = 0; float sOwn = 0.0f; ull f0own;                         \
    half_fma(pb + (BUF) * 48 + ownOff, Eown, eOwn, a0, a1, sOwn, f0own);      \
    bar_sync64(myBar);                                                        \
    ull b0 = 0, b1 = 0; float sOth = 0.0f; ull f0oth;                         \
    half_fma(pb + (BUF) * 48 + othOff, Eoth, eOth, b0, b1, sOth, f0oth);      \
    float tail = eff;                                                         \
    if (RENORM) {                                                             \
        const ull h0 = half ? f0oth : f0own;                                  \
        const unsigned p0b = (unsigned)(h0 & 0xFFFFFFFFull);                  \
        int k = (int)((p0b >> 23) & 0xFF) - 127;                              \
        k = max(-120, min(120, k));                                           \
        Ks += k;                                                              \
        tail = eff * __int_as_float((unsigned)(127 - k) << 23);               \
    }                                                                         \
    const ull r = fadd2(fadd2(a0, b0), fadd2(a1, b1));                        \
    float lo, hi; unpack2(r, lo, hi);                                         \
    p = ((lo + hi) + (sOwn + sOth)) * tail;                                   \
} while (0)

#define BWD_STEP(BUF, RENORM, TT) do {                                        \
    const float q = bc * efc;                                                 \
    if (lane < 17) wb[(BUF) * 48 + ownOff + lane] = q;                        \
    __syncwarp();                                                             \
    efc = sh[EF + ((TT) - 1) * T_ + j];                                       \
    ull a0 = 0, a1 = 0; float sOwn = 0.0f; ull f0own;                         \
    half_fma(wb + (BUF) * 48 + ownOff, Rown, rOwn, a0, a1, sOwn, f0own);      \
    bar_sync64(myBar);                                                        \
    ull b0 = 0, b1 = 0; float sOth = 0.0f; ull f0oth;                         \
    half_fma(wb + (BUF) * 48 + othOff, Roth, rOth, b0, b1, sOth, f0oth);      \
    const ull r = fadd2(fadd2(a0, b0), fadd2(a1, b1));                        \
    float lo, hi; unpack2(r, lo, hi);                                         \
    const float y = (lo + hi) + (sOwn + sOth);                                \
    if (RENORM) {                                                             \
        const ull h0 = half ? f0oth : f0own;                                  \
        const unsigned p0b = (unsigned)(h0 & 0xFFFFFFFFull);                  \
        int k = (int)((p0b >> 23) & 0xFF) - 127;                              \
        k = max(-120, min(120, k));                                           \
        Ks += k;                                                              \
        bc = y * __int_as_float((unsigned)(127 - k) << 23);                   \
    } else {                                                                  \
        bc = y;                                                               \
    }                                                                         \
} while (0)

// Forward chain: p_t[j] = ef_t[j] * sum_i p_{t-1}[i] E[i][j], t = tlo..thi.
__device__ __forceinline__ int run_fwd_chain(
    float* __restrict__ sh, int lane, int half, int j,
    int myBar, float* __restrict__ pb,
    float pinit, int tlo, int thi, float* __restrict__ outv)
{
    ull E0[8], E1[8];
    #pragma unroll
    for (int m = 0; m < 8; m++) {
        E0[m] = pack2(__expf(sh[TR + (2 * m) * T_ + j]),
                      __expf(sh[TR + (2 * m + 1) * T_ + j]));
        E1[m] = pack2(__expf(sh[TR + (17 + 2 * m) * T_ + j]),
                      __expf(sh[TR + (18 + 2 * m) * T_ + j]));
    }
    const float e16 = __expf(sh[TR + 16 * T_ + j]);
    const float e33 = __expf(sh[TR + 33 * T_ + j]);
    const ull*  Eown = half ? E1 : E0;
    const ull*  Eoth = half ? E0 : E1;
    const float eOwn = half ? e33 : e16;
    const float eOth = half ? e16 : e33;
    const int   ownOff = half * 24, othOff = 24 - half * 24;

    float p = pinit;
    int Ks = 0;
    int t = tlo;
    while (t + 1 <= thi) { FWD_STEP(0, true, t); FWD_STEP(1, false, t + 1); t += 2; }
    if (t <= thi) { FWD_STEP(0, true, t); }
    if (lane < 17) outv[j] = p;
    return Ks;
}

// Backward chain: y_{t-1}[i] = sum_j E[i][j] ef_t[j] y_t[j], t = thi down to tloex+1.
__device__ __forceinline__ int run_bwd_chain(
    float* __restrict__ sh, int lane, int half, int j,
    int myBar, float* __restrict__ wb,
    float bcinit, int tloex, int thi, float* __restrict__ outv)
{
    ull R0[8], R1[8];
    #pragma unroll
    for (int m = 0; m < 8; m++) {
        R0[m] = pack2(__expf(sh[TR + j * T_ + (2 * m)]),
                      __expf(sh[TR + j * T_ + (2 * m + 1)]));
        R1[m] = pack2(__expf(sh[TR + j * T_ + (17 + 2 * m)]),
                      __expf(sh[TR + j * T_ + (18 + 2 * m)]));
    }
    const float r16 = __expf(sh[TR + j * T_ + 16]);
    const float r33 = __expf(sh[TR + j * T_ + 33]);
    const ull*  Rown = half ? R1 : R0;
    const ull*  Roth = half ? R0 : R1;
    const float rOwn = half ? r33 : r16;
    const float rOth = half ? r16 : r33;
    const int   ownOff = half * 24, othOff = 24 - half * 24;

    float bc  = bcinit;
    float efc = sh[EF + thi * T_ + j];
    int Ks = 0;
    int t = thi;
    while (t - 1 > tloex) { BWD_STEP(0, true, t); BWD_STEP(1, false, t - 1); t -= 2; }
    if (t > tloex) { BWD_STEP(0, true, t); }
    if (lane < 17) outv[j] = bc;
    return Ks;
}

__global__ void __launch_bounds__(NTHREADS, 1)
crf_kernel(const float* __restrict__ feats,
           const float* __restrict__ transitions,
           const int*   __restrict__ mask,
           const int*   __restrict__ tags,
           float*       __restrict__ out)
{
    extern __shared__ float sh[];
    const int tid  = threadIdx.x;
    const int lane = tid & 31;
    const int wid  = tid >> 5;
    const int b    = blockIdx.x;

    // ---- stage exp(feats[b]) (72KB) + raw transitions into smem, coalesced ----
    {
        const float4* fsrc = (const float4*)(feats + (size_t)b * (S_ * T_));
        float4* fdst = (float4*)(sh + EF);
        for (int i = tid; i < (S_ * T_ / 4); i += NTHREADS) {
            float4 v = fsrc[i];
            v.x = __expf(v.x); v.y = __expf(v.y);
            v.z = __expf(v.z); v.w = __expf(v.w);
            fdst[i] = v;
        }
        const float4* tsrc = (const float4*)transitions;
        float4* tdst = (float4*)(sh + TR);
        for (int i = tid; i < (T_ * T_ / 4); i += NTHREADS)
            tdst[i] = tsrc[i];
    }

    // ---- sequence length (mask is a contiguous prefix) ----
    int lsum = 0;
    {
        const int* mrow = mask + b * S_;
        for (int i = tid; i < S_; i += NTHREADS) lsum += mrow[i];
    }
    #pragma unroll
    for (int off = 16; off > 0; off >>= 1)
        lsum += __shfl_xor_sync(0xFFFFFFFFu, lsum, off);
    if (lane == 0) ((int*)(sh + RD))[wid] = lsum;
    __syncthreads();
    int len = 0;
    #pragma unroll
    for (int i = 0; i < 10; i++) len += ((const int*)(sh + RD))[i];
    const int n1 = len / 3;            // A = [0, n1]
    const int n2 = (2 * len) / 3;      // B = (n1, n2],  C = (n2, len)

    const int chain = wid >> 1;                    // 0..3 chains; 4 = gold
    const int half  = wid & 1;
    const int l     = (lane < 17) ? lane : 16;     // pad lanes duplicate col 16
    const int j     = half * 17 + l;               // this lane's column/state

    if (chain < 4) {
        const int myBar = 1 + chain;               // bars 1..4, one per chain
        float* pb   = sh + PP + 96 * chain;
        float* outv = sh + MV + 40 * chain;
        int Ks;
        if (chain == 0) {
            // alpha over A: t = 1..n1
            const float pinit = sh[EF + j] * __expf(sh[TR + STARTT * T_ + j]);
            Ks = run_fwd_chain(sh, lane, half, j, myBar, pb, pinit, 1, n1, outv);
        } else if (chain == 1) {
            // a_B over B (fwd from ones): t = n1+1..n2
            Ks = run_fwd_chain(sh, lane, half, j, myBar, pb, 1.0f, n1 + 1, n2, outv);
        } else if (chain == 2) {
            // b_B over B (bwd from ones): t = n2 down to n1+1
            Ks = run_bwd_chain(sh, lane, half, j, myBar, pb, 1.0f, n1, n2, outv);
        } else {
            // beta over C: t = len-1 down to n2+1
            const float bcinit = __expf(sh[TR + j * T_ + ENDT]);
            Ks = run_bwd_chain(sh, lane, half, j, myBar, pb, bcinit, n2, len - 1, outv);
        }
        if (half == 0 && lane == 0) ((int*)(sh + RD))[16 + chain] = Ks;
    } else {
        // ===== warps 8,9: gold score (concurrent with all chains) =====
        const int*   trow = tags  + b * S_;
        const float* frow = feats + (size_t)b * (S_ * T_);
        float g = 0.0f;
        for (int t = tid - 256; t < len; t += 64) {
            const int tg = trow[t];
            const int pv = (t == 0) ? STARTT : trow[t - 1];
            g += __ldg(frow + t * T_ + tg) + sh[TR + pv * T_ + tg];
        }
        #pragma unroll
        for (int off = 16; off > 0; off >>= 1)
            g += __shfl_xor_sync(0xFFFFFFFFu, g, off);
        if (lane == 0) sh[RD + 12 + (wid - 8)] = g;
        bar_sync64(5);
        if (tid == 256) {
            const float endE = sh[TR + trow[len - 1] * T_ + ENDT];
            sh[RD + 14] = sh[RD + 12] + sh[RD + 13] + endE;
        }
    }

    __syncthreads();

    // ---- combine (warp 0):  Z = (alpha.b_B)(a_B.beta) / sum(a_B) ----
    if (wid == 0) {
        const int j0 = 2 * l;
        const float2 av  = *(const float2*)(sh + MV + 0 * 40 + j0);  // alpha_n1
        const float2 abv = *(const float2*)(sh + MV + 1 * 40 + j0);  // a_B
        const float2 bbv = *(const float2*)(sh + MV + 2 * 40 + j0);  // b_B
        const float2 bv  = *(const float2*)(sh + MV + 3 * 40 + j0);  // beta_n2
        const bool ok = (lane < 17);
        float c1 = ok ? (av.x * bbv.x + av.y * bbv.y) : 0.0f;
        float c2 = ok ? (abv.x * bv.x + abv.y * bv.y) : 0.0f;
        float c4 = ok ? (abv.x + abv.y) : 0.0f;
        #pragma unroll
        for (int off = 16; off > 0; off >>= 1) {
            c1 += __shfl_xor_sync(0xFFFFFFFFu, c1, off);
            c2 += __shfl_xor_sync(0xFFFFFFFFu, c2, off);
            c4 += __shfl_xor_sync(0xFFFFFFFFu, c4, off);
        }
        if (lane == 0) {
            const int* Kp = (const int*)(sh + RD);
            const int Ks = Kp[16 + 0] + Kp[16 + 2] + Kp[16 + 3];   // a_B scale cancels
            const float fwd = __logf(c1) + __logf(c2) - __logf(c4)
                            + (float)Ks * 0.6931471805599453f;
            g_partial[b] = fwd - sh[RD + 14];
        }
    }

    // ---- fused finalize: last block reduces all partials (deterministic) ----
    __shared__ int lastflag;
    __threadfence();
    if (tid == 0) lastflag = (atomicAdd(&g_count, 1) == B_ - 1);
    __syncthreads();
    if (lastflag) {
        __threadfence();
        volatile const float* gp = g_partial;
        if (tid < B_) sh[tid] = gp[tid];      // reuse EF region as scratch
        __syncthreads();
        #pragma unroll
        for (int off = 64; off > 0; off >>= 1) {
            if (tid < off) sh[tid] += sh[tid + off];
            __syncthreads();
        }
        if (tid == 0) {
            out[0] = sh[0] * (1.0f / (float)B_);
            g_count = 0;   // reset for next graph replay
        }
    }
}

extern "C" void kernel_launch(void* const* d_in, const int* in_sizes, int n_in,
                              void* d_out, int out_size)
{
    const float* feats = (const float*)d_in[0];
    const float* trans = (const float*)d_in[1];
    const int*   mask  = (const int*)d_in[2];
    const int*   tags  = (const int*)d_in[3];

    cudaFuncSetAttribute((const void*)crf_kernel,
                         cudaFuncAttributeMaxDynamicSharedMemorySize, SMEM_BYTES);
    crf_kernel<<<B_, NTHREADS, SMEM_BYTES>>>(feats, trans, mask, tags, (float*)d_out);
}

// round 16
// speedup vs baseline: 1.0812x; 1.0729x over previous
#include <cuda_runtime.h>
#include <math.h>

#define B_   128
#define S_   512
#define T_   36
#define STARTT 34
#define ENDT   35
#define NTHREADS 256

// dynamic smem layout (floats):
//  [0, 18432)        exp(feats) (S*T)   (reused as finalize scratch)
//  [18432, 19728)    raw transitions (36*36)
//  [19728, 20304)    ping-pong buffers: 6 chains x 96 (2 bufs x 48, slots 34..47 zero)
//  [20304, 20544)    meet vectors: 6 x 40  (chain c output at MV + 40c, 34 used)
//  [20544, 20576)    RD: ints [0..7] len partials, floats [8..9] gold parts,
//                    [10] gold total, ints [12..17] per-chain Ks
#define EF  0
#define TR  18432
#define PP  19728
#define MV  20304
#define RD  20544
#define SMEM_FLOATS 20576
#define SMEM_BYTES  (SMEM_FLOATS * 4)

typedef unsigned long long ull;

__device__ float g_partial[B_];
__device__ int   g_count = 0;

__device__ __forceinline__ ull ffma2(ull a, ull b, ull c) {
    ull d;
    asm("fma.rn.f32x2 %0, %1, %2, %3;" : "=l"(d) : "l"(a), "l"(b), "l"(c));
    return d;
}
__device__ __forceinline__ ull fadd2(ull a, ull b) {
    ull d;
    asm("add.rn.f32x2 %0, %1, %2;" : "=l"(d) : "l"(a), "l"(b));
    return d;
}
__device__ __forceinline__ ull pack2(float lo, float hi) {
    ull d;
    asm("mov.b64 %0, {%1, %2};" : "=l"(d) : "f"(lo), "f"(hi));
    return d;
}
__device__ __forceinline__ void unpack2(ull v, float& lo, float& hi) {
    asm("mov.b64 {%0, %1}, %2;" : "=f"(lo), "=f"(hi) : "l"(v));
}

// Full 34-dot for this lane's column pair, cross-packed (round-3/5 proven body).
// sbuf must be zero-padded through slot 35. Returns V[0].x (packed v0,v1) for renorm.
__device__ __forceinline__ void matvec34(const float* __restrict__ sbuf,
                                         const ull* __restrict__ Ea,
                                         const ull* __restrict__ Eb,
                                         float& r0, float& r1, ull& first)
{
    const ulonglong2* Vp = (const ulonglong2*)sbuf;
    ulonglong2 V[9];
    #pragma unroll
    for (int q = 0; q < 9; q++) V[q] = Vp[q];

    ull accA[3] = {0, 0, 0}, accB[3] = {0, 0, 0};
    #pragma unroll
    for (int m = 0; m < 17; m++) {
        const ull pm = (m & 1) ? V[m >> 1].y : V[m >> 1].x;
        accA[m % 3] = ffma2(pm, Ea[m], accA[m % 3]);
        accB[m % 3] = ffma2(pm, Eb[m], accB[m % 3]);
    }
    const ull rA = fadd2(fadd2(accA[0], accA[1]), accA[2]);
    const ull rB = fadd2(fadd2(accB[0], accB[1]), accB[2]);
    float a0, a1, b0, b1;
    unpack2(rA, a0, a1);
    unpack2(rB, b0, b1);
    r0 = a0 + b1;
    r1 = a1 + b0;
    first = V[0].x;
}

// ---- one fwd step; REN = power-of-two renorm (every 2nd step) ----
#define FWD_ONE(BUF, REN, TT) do {                                            \
    const float2 ef2 = *(const float2*)(sh + EF + (TT) * T_ + j0);            \
    float r0, r1; ull f0;                                                     \
    matvec34(pb + (BUF) * 48, EA, EB, r0, r1, f0);                            \
    float sx = ef2.x, sy = ef2.y;                                             \
    if (REN) {                                                                \
        const unsigned p0 = (unsigned)(f0 & 0xFFFFFFFFull);                   \
        int k = (int)((p0 >> 23) & 0xFF) - 127;                               \
        k = max(-120, min(120, k));                                           \
        Ks += k;                                                              \
        const float sc = __int_as_float((unsigned)(127 - k) << 23);           \
        sx *= sc; sy *= sc;                                                   \
    }                                                                         \
    pc.x = r0 * sx;  pc.y = r1 * sy;                                          \
    if (lane < 17) *(float2*)(pb + ((BUF) ^ 1) * 48 + j0) = pc;               \
    __syncwarp();                                                             \
} while (0)

// ---- one bwd step; ef2 holds ef_t (prefetched), reloads for t-1 ----
#define BWD_ONE(BUF, REN, TT) do {                                            \
    float2 q; q.x = bc.x * ef2.x;  q.y = bc.y * ef2.y;                        \
    if (lane < 17) *(float2*)(wb + (BUF) * 48 + j0) = q;                      \
    __syncwarp();                                                             \
    ef2 = *(const float2*)(sh + EF + ((TT) - 1) * T_ + j0);                   \
    float r0, r1; ull f0;                                                     \
    matvec34(wb + (BUF) * 48, TA, TB, r0, r1, f0);                            \
    if (REN) {                                                                \
        const unsigned p0 = (unsigned)(f0 & 0xFFFFFFFFull);                   \
        int k = (int)((p0 >> 23) & 0xFF) - 127;                               \
        k = max(-120, min(120, k));                                           \
        Ks += k;                                                              \
        const float sc = __int_as_float((unsigned)(127 - k) << 23);           \
        bc.x = r0 * sc;  bc.y = r1 * sc;                                      \
    } else {                                                                  \
        bc.x = r0;  bc.y = r1;                                                \
    }                                                                         \
} while (0)

// Forward chain: p_t[j] = ef_t[j] * sum_i p_{t-1}[i] E[i][j], t = tlo..thi.
__device__ __forceinline__ int run_fwd_chain(const float* __restrict__ sh,
                                             float* __restrict__ pb,
                                             float* __restrict__ outv,
                                             int lane, int j0, int j1,
                                             float2 pc, int tlo, int thi)
{
    // cross-packed columns: EA[m]=(E[2m][j0],E[2m+1][j1]) EB[m]=(E[2m][j1],E[2m+1][j0])
    ull EA[17], EB[17];
    #pragma unroll
    for (int m = 0; m < 17; m++) {
        const float t00 = __expf(sh[TR + (2 * m)     * T_ + j0]);
        const float t01 = __expf(sh[TR + (2 * m)     * T_ + j1]);
        const float t10 = __expf(sh[TR + (2 * m + 1) * T_ + j0]);
        const float t11 = __expf(sh[TR + (2 * m + 1) * T_ + j1]);
        EA[m] = pack2(t00, t11);
        EB[m] = pack2(t01, t10);
    }
    if (lane < 17) *(float2*)(pb + j0) = pc;
    __syncwarp();

    int Ks = 0;
    int t = tlo;
    while (t + 1 <= thi) { FWD_ONE(0, true, t); FWD_ONE(1, false, t + 1); t += 2; }
    if (t <= thi) { FWD_ONE(0, true, t); }
    if (lane < 17) *(float2*)(outv + j0) = pc;
    return Ks;
}

// Backward chain: y_{t-1}[i] = sum_j E[i][j] ef_t[j] y_t[j], t = thi down to tloex+1.
__device__ __forceinline__ int run_bwd_chain(const float* __restrict__ sh,
                                             float* __restrict__ wb,
                                             float* __restrict__ outv,
                                             int lane, int j0, int j1,
                                             float2 bc, int tloex, int thi)
{
    // cross-packed rows: TA[m]=(E[j0][2m],E[j1][2m+1]) TB[m]=(E[j1][2m],E[j0][2m+1])
    ull TA[17], TB[17];
    #pragma unroll
    for (int m = 0; m < 17; m++) {
        const float t00 = __expf(sh[TR + j0 * T_ + (2 * m)]);
        const float t01 = __expf(sh[TR + j0 * T_ + (2 * m + 1)]);
        const float t10 = __expf(sh[TR + j1 * T_ + (2 * m)]);
        const float t11 = __expf(sh[TR + j1 * T_ + (2 * m + 1)]);
        TA[m] = pack2(t00, t11);
        TB[m] = pack2(t10, t01);
    }
    float2 ef2 = *(const float2*)(sh + EF + thi * T_ + j0);

    int Ks = 0;
    int t = thi;
    while (t - 1 > tloex) { BWD_ONE(0, true, t); BWD_ONE(1, false, t - 1); t -= 2; }
    if (t > tloex) { BWD_ONE(0, true, t); }
    if (lane < 17) *(float2*)(outv + j0) = bc;
    return Ks;
}

__global__ void __launch_bounds__(NTHREADS, 1)
crf_kernel(const float* __restrict__ feats,
           const float* __restrict__ transitions,
           const int*   __restrict__ mask,
           const int*   __restrict__ tags,
           float*       __restrict__ out)
{
    extern __shared__ float sh[];
    const int tid  = threadIdx.x;
    const int lane = tid & 31;
    const int wid  = tid >> 5;
    const int b    = blockIdx.x;

    // ---- stage exp(feats[b]) (72KB) + raw transitions into smem, coalesced ----
    {
        const float4* fsrc = (const float4*)(feats + (size_t)b * (S_ * T_));
        float4* fdst = (float4*)(sh + EF);
        #pragma unroll
        for (int i = 0; i < (S_ * T_ / 4) / NTHREADS; i++) {   // 18 iters
            float4 v = fsrc[tid + i * NTHREADS];
            v.x = __expf(v.x); v.y = __expf(v.y);
            v.z = __expf(v.z); v.w = __expf(v.w);
            fdst[tid + i * NTHREADS] = v;
        }
        const float4* tsrc = (const float4*)transitions;
        float4* tdst = (float4*)(sh + TR);
        for (int i = tid; i < (T_ * T_ / 4); i += NTHREADS)
            tdst[i] = tsrc[i];
        // zero-pad slots 34..47 of all 12 ping-pong buffers (never rewritten)
        if (tid < 168) {
            const int c = tid / 28, r = tid % 28;
            const int bf = r / 14, s = r % 14;
            sh[PP + 96 * c + 48 * bf + 34 + s] = 0.0f;
        }
    }

    // ---- sequence length (mask is a contiguous prefix) ----
    int lsum = 0;
    {
        const int* mrow = mask + b * S_;
        #pragma unroll
        for (int i = 0; i < 2; i++) lsum += mrow[tid + i * NTHREADS];
    }
    #pragma unroll
    for (int off = 16; off > 0; off >>= 1)
        lsum += __shfl_xor_sync(0xFFFFFFFFu, lsum, off);
    if (lane == 0) ((int*)(sh + RD))[wid] = lsum;
    __syncthreads();
    int len = 0;
    #pragma unroll
    for (int i = 0; i < 8; i++) len += ((const int*)(sh + RD))[i];
    const int n1 = len >> 2;       // A = [0, n1]
    const int n2 = len >> 1;       // B = (n1, n2]
    const int n3 = n1 + n2;        // C = (n2, n3],  D = (n3, len)

    const int l  = (lane < 17) ? lane : 16;   // pad lanes duplicate pair 16
    const int j0 = 2 * l, j1 = 2 * l + 1;

    if (wid < 6) {
        // ===== six independent single-warp chains (syncwarp-only; no named bars) =====
        float* pb   = sh + PP + 96 * wid;
        float* outv = sh + MV + 40 * wid;
        int Ks;
        if (wid == 0) {
            // alpha over A: t = 1..n1
            float2 pinit;
            pinit.x = sh[EF + j0] * __expf(sh[TR + STARTT * T_ + j0]);
            pinit.y = sh[EF + j1] * __expf(sh[TR + STARTT * T_ + j1]);
            Ks = run_fwd_chain(sh, pb, outv, lane, j0, j1, pinit, 1, n1);
        } else if (wid == 1) {
            // a_B over B (fwd from ones)
            Ks = run_fwd_chain(sh, pb, outv, lane, j0, j1,
                               make_float2(1.f, 1.f), n1 + 1, n2);
        } else if (wid == 2) {
            // b_B over B (bwd from ones)
            Ks = run_bwd_chain(sh, pb, outv, lane, j0, j1,
                               make_float2(1.f, 1.f), n1, n2);
        } else if (wid == 3) {
            // a_C over C (fwd from ones)
            Ks = run_fwd_chain(sh, pb, outv, lane, j0, j1,
                               make_float2(1.f, 1.f), n2 + 1, n3);
        } else if (wid == 4) {
            // b_C over C (bwd from ones)
            Ks = run_bwd_chain(sh, pb, outv, lane, j0, j1,
                               make_float2(1.f, 1.f), n2, n3);
        } else {
            // beta over D: t = len-1 down to n3+1
            float2 binit;
            binit.x = __expf(sh[TR + j0 * T_ + ENDT]);
            binit.y = __expf(sh[TR + j1 * T_ + ENDT]);
            Ks = run_bwd_chain(sh, pb, outv, lane, j0, j1, binit, n3, len - 1);
        }
        if (lane == 0) ((int*)(sh + RD))[12 + wid] = Ks;
    } else {
        // ===== warps 6,7: gold score (concurrent with all chains) =====
        const int*   trow = tags  + b * S_;
        const float* frow = feats + (size_t)b * (S_ * T_);
        float g = 0.0f;
        for (int t = tid - 192; t < len; t += 64) {
            const int tg = trow[t];
            const int pv = (t == 0) ? STARTT : trow[t - 1];
            g += __ldg(frow + t * T_ + tg) + sh[TR + pv * T_ + tg];
        }
        #pragma unroll
        for (int off = 16; off > 0; off >>= 1)
            g += __shfl_xor_sync(0xFFFFFFFFu, g, off);
        if (lane == 0) sh[RD + 8 + (wid - 6)] = g;
        asm volatile("bar.sync 1, 64;" ::: "memory");
        if (tid == 192) {
            const float endE = sh[TR + trow[len - 1] * T_ + ENDT];
            sh[RD + 10] = sh[RD + 8] + sh[RD + 9] + endE;
        }
    }

    __syncthreads();

    // ---- combine (warp 0), validated exact in round 12:
    //  Z = (alpha.b_B)(a_B.b_C)(a_C.beta) / (sum a_B * sum a_C)
    if (wid == 0) {
        const int jj = 2 * l;
        const float2 av  = *(const float2*)(sh + MV + 0 * 40 + jj);  // alpha_n1
        const float2 abv = *(const float2*)(sh + MV + 1 * 40 + jj);  // a_B
        const float2 bbv = *(const float2*)(sh + MV + 2 * 40 + jj);  // b_B
        const float2 acv = *(const float2*)(sh + MV + 3 * 40 + jj);  // a_C
        const float2 bcv = *(const float2*)(sh + MV + 4 * 40 + jj);  // b_C
        const float2 bv  = *(const float2*)(sh + MV + 5 * 40 + jj);  // beta_n3
        const bool ok = (lane < 17);
        float c1 = ok ? (av.x * bbv.x + av.y * bbv.y) : 0.0f;
        float c2 = ok ? (abv.x * bcv.x + abv.y * bcv.y) : 0.0f;
        float c3 = ok ? (acv.x * bv.x + acv.y * bv.y) : 0.0f;
        float c4 = ok ? (abv.x + abv.y) : 0.0f;
        float c5 = ok ? (acv.x + acv.y) : 0.0f;
        #pragma unroll
        for (int off = 16; off > 0; off >>= 1) {
            c1 += __shfl_xor_sync(0xFFFFFFFFu, c1, off);
            c2 += __shfl_xor_sync(0xFFFFFFFFu, c2, off);
            c3 += __shfl_xor_sync(0xFFFFFFFFu, c3, off);
            c4 += __shfl_xor_sync(0xFFFFFFFFu, c4, off);
            c5 += __shfl_xor_sync(0xFFFFFFFFu, c5, off);
        }
        if (lane == 0) {
            const int* Kp = (const int*)(sh + RD);
            const int Ks = Kp[12 + 0] + Kp[12 + 2] + Kp[12 + 4] + Kp[12 + 5];
            const float fwd = __logf(c1) + __logf(c2) + __logf(c3)
                            - __logf(c4) - __logf(c5)
                            + (float)Ks * 0.6931471805599453f;
            g_partial[b] = fwd - sh[RD + 10];
        }
    }

    // ---- fused finalize: last block reduces all partials (deterministic) ----
    __shared__ int lastflag;
    __threadfence();
    if (tid == 0) lastflag = (atomicAdd(&g_count, 1) == B_ - 1);
    __syncthreads();
    if (lastflag) {
        __threadfence();
        volatile const float* gp = g_partial;
        if (tid < B_) sh[tid] = gp[tid];      // reuse EF region as scratch
        __syncthreads();
        #pragma unroll
        for (int off = 64; off > 0; off >>= 1) {
            if (tid < off) sh[tid] += sh[tid + off];
            __syncthreads();
        }
        if (tid == 0) {
            out[0] = sh[0] * (1.0f / (float)B_);
            g_count = 0;   // reset for next graph replay
        }
    }
}

extern "C" void kernel_launch(void* const* d_in, const int* in_sizes, int n_in,
                              void* d_out, int out_size)
{
    const float* feats = (const float*)d_in[0];
    const float* trans = (const float*)d_in[1];
    const int*   mask  = (const int*)d_in[2];
    const int*   tags  = (const int*)d_in[3];

    cudaFuncSetAttribute((const void*)crf_kernel,
                         cudaFuncAttributeMaxDynamicSharedMemorySize, SMEM_BYTES);
    crf_kernel<<<B_, NTHREADS, SMEM_BYTES>>>(feats, trans, mask, tags, (float*)d_out);
}